// round 1
// baseline (speedup 1.0000x reference)
#include <cuda_runtime.h>
#include <math.h>

#define BETA 0.1f

// One block per (b,p) tile. 256 threads.
// Input layout: x_cat[b, a, k] with a = 2p + s, so the h-row for tile bp
// starts at x + bp*128 and the v-row at x + bp*128 + 64. Same for noise.
// Output: places at out + bp*4096, sampled_points at out + half + bp*4096.
__global__ __launch_bounds__(256, 8)
void spatial_sampler_kernel(const float* __restrict__ x_cat,
                            const float* __restrict__ noise,
                            float* __restrict__ out,
                            long long half_elems)
{
    __shared__ float sx[128];   // [0:64) = h row, [64:128) = v row
    __shared__ float ss[128];   // masked (sampled) rows
    __shared__ float wmax[4];   // per-warp maxima

    const int bp  = blockIdx.x;          // 0 .. 8191
    const int tid = threadIdx.x;

    const float* xrow = x_cat + (long long)bp * 128;
    const float* nrow = noise + (long long)bp * 128;

    // --- load + log_pdf + per-row max (rows are 64 wide = 2 warps each) ---
    float lp = -INFINITY;
    float xv = 0.f;
    if (tid < 128) {
        xv = xrow[tid];
        lp = logf(xv) + BETA * nrow[tid];
        sx[tid] = xv;
    }
    // warp-level max
    float m = lp;
    #pragma unroll
    for (int off = 16; off > 0; off >>= 1)
        m = fmaxf(m, __shfl_xor_sync(0xffffffffu, m, off));
    if (tid < 128 && (tid & 31) == 0)
        wmax[tid >> 5] = m;
    __syncthreads();

    if (tid < 128) {
        // row 0 (h) spans warps 0,1; row 1 (v) spans warps 2,3
        float rowmax = (tid < 64) ? fmaxf(wmax[0], wmax[1])
                                  : fmaxf(wmax[2], wmax[3]);
        ss[tid] = (lp == rowmax) ? xv : 0.f;
    }
    __syncthreads();

    // --- write both 64x64 tiles, float4-vectorized, coalesced ---
    float*       places  = out + (long long)bp * 4096;
    float*       sampled = out + half_elems + (long long)bp * 4096;
    const float4* v4  = reinterpret_cast<const float4*>(&sx[64]);
    const float4* sv4 = reinterpret_cast<const float4*>(&ss[64]);
    float4* p4 = reinterpret_cast<float4*>(places);
    float4* s4 = reinterpret_cast<float4*>(sampled);

    #pragma unroll
    for (int i = tid; i < 1024; i += 256) {
        const int j  = i >> 4;     // row 0..63
        const int c4 = i & 15;     // float4 column 0..15

        const float hj = sx[j];
        float4 vv = v4[c4];
        float4 o;
        o.x = hj * vv.x; o.y = hj * vv.y; o.z = hj * vv.z; o.w = hj * vv.w;
        p4[i] = o;

        const float shj = ss[j] * 100.0f;
        float4 sv = sv4[c4];
        float4 so;
        so.x = shj * sv.x; so.y = shj * sv.y; so.z = shj * sv.z; so.w = shj * sv.w;
        s4[i] = so;
    }
}

extern "C" void kernel_launch(void* const* d_in, const int* in_sizes, int n_in,
                              void* d_out, int out_size)
{
    const float* x_cat = (const float*)d_in[0];
    const float* noise = (const float*)d_in[1];
    float* out = (float*)d_out;

    const long long half = (long long)out_size / 2;   // 33,554,432
    const int tiles = in_sizes[0] / 128;              // 8192 (b,p) tiles

    spatial_sampler_kernel<<<tiles, 256>>>(x_cat, noise, out, half);
}